// round 17
// baseline (speedup 1.0000x reference)
#include <cuda_runtime.h>
#include <cuda_bf16.h>
#include <math.h>
#include <stdint.h>

// Problem constants
#define BHX   32
#define SEQ   4096
#define DDIM  64
#define MDIM  266
#define NTIL  34           // 8-wide N-tiles for dash (272)
#define JPAD  272          // padded feature dim (17 k-tiles of 16)
#define PPAD  288
#define CTXW  65
#define KSPL  8
#define KROWS (SEQ / KSPL)
#define EPSF  1e-4f
#define DNORM 0.35355339059327373f
#define CTXTOT (BHX * MDIM * CTXW)
#define KPW   (SEQ / 2)    // words per kpT row (i-pairs)
#define QPW   (JPAD / 2)   // words per qp row (j-pairs) = 136
#define VTR   72           // vT rows: 64 v + 1 ones + 7 zero (n-tiles of 8)
#define CTW   (JPAD / 2)   // words per ctxT row

// -------- persistent scratch (device globals: allocation-free) --------
__device__ float        g_dash [(size_t)BHX * SEQ * MDIM];   // qd (normal layout)
__device__ float        g_dashT[(size_t)BHX * JPAD * SEQ];   // kd (transposed [j][i])
__device__ float        g_diag_k[BHX * SEQ];
__device__ float        g_diag_q[BHX * SEQ];
__device__ float        g_rowmax[BHX * SEQ];
__device__ float        g_ctx[CTXTOT];
__device__ float        g_ctx_part[KSPL * CTXTOT];
__device__ unsigned int g_kstab_bits;
// packed bf16 pairs (2 per 32-bit word)
__device__ uint4        g_khi4[(size_t)BHX * SEQ * 8];       // dash A operands
__device__ uint4        g_klo4[(size_t)BHX * SEQ * 8];
__device__ uint4        g_qhi4[(size_t)BHX * SEQ * 8];
__device__ uint4        g_qlo4[(size_t)BHX * SEQ * 8];
__device__ uint4        g_phi4[PPAD * 8];
__device__ uint4        g_plo4[PPAD * 8];
__device__ unsigned int g_kpT_hi[(size_t)BHX * JPAD * KPW]; // exp(kd) transposed
__device__ unsigned int g_kpT_lo[(size_t)BHX * JPAD * KPW];
__device__ unsigned int g_qp_hi [(size_t)BHX * SEQ * QPW];  // exp(qd)
__device__ unsigned int g_qp_lo [(size_t)BHX * SEQ * QPW];
__device__ unsigned int g_vT_hi [(size_t)BHX * VTR * KPW];  // v transposed (+ones row)
__device__ unsigned int g_vT_lo [(size_t)BHX * VTR * KPW];
__device__ unsigned int g_cT_hi [(size_t)BHX * VTR * CTW];  // ctx transposed
__device__ unsigned int g_cT_lo [(size_t)BHX * VTR * CTW];

__device__ __forceinline__ unsigned int enc_f(float f) {
    int i = __float_as_int(f);
    return (i >= 0) ? ((unsigned int)i | 0x80000000u) : (unsigned int)(~i);
}
__device__ __forceinline__ float dec_f(unsigned int u) {
    int i = (u & 0x80000000u) ? (int)(u & 0x7fffffffu) : (~(int)u);
    return __int_as_float(i);
}
__device__ __forceinline__ uint32_t pack_split(float a, float b, uint32_t& lo) {
    __nv_bfloat16 ha = __float2bfloat16(a), hb = __float2bfloat16(b);
    __nv_bfloat16 la = __float2bfloat16(a - __bfloat162float(ha));
    __nv_bfloat16 lb = __float2bfloat16(b - __bfloat162float(hb));
    lo = ((uint32_t)__bfloat16_as_ushort(lb) << 16) | __bfloat16_as_ushort(la);
    return ((uint32_t)__bfloat16_as_ushort(hb) << 16) | __bfloat16_as_ushort(ha);
}

__global__ void reset_kernel() { g_kstab_bits = 0x007FFFFFu; }

// m16n8k16 bf16 MMA, fp32 accumulate (sm_80+ PTX; not sm_103a-gated)
__device__ __forceinline__ void mma16816(float* d, const uint32_t* a, const uint32_t* b) {
    asm volatile(
        "mma.sync.aligned.m16n8k16.row.col.f32.bf16.bf16.f32 "
        "{%0,%1,%2,%3}, {%4,%5,%6,%7}, {%8,%9}, {%0,%1,%2,%3};"
        : "+f"(d[0]), "+f"(d[1]), "+f"(d[2]), "+f"(d[3])
        : "r"(a[0]), "r"(a[1]), "r"(a[2]), "r"(a[3]), "r"(b[0]), "r"(b[1]));
}

// ---------------------------------------------------------------------
// preps: hi/lo bf16 of DNORM*A + per-row diag; P hi/lo
// ---------------------------------------------------------------------
template<bool IS_QUERY>
__global__ void __launch_bounds__(256) prep_qk(const float* __restrict__ src)
{
    const int warp = threadIdx.x >> 5, lane = threadIdx.x & 31;
    const size_t row = (size_t)blockIdx.x * 8 + warp;
    const float2 v = reinterpret_cast<const float2*>(src)[row * 32 + lane];
    float s1 = DNORM * v.x, s2 = DNORM * v.y;
    uint32_t lo, hi = pack_split(s1, s2, lo);
    unsigned int* dhi = reinterpret_cast<unsigned int*>(IS_QUERY ? g_qhi4 : g_khi4);
    unsigned int* dlo = reinterpret_cast<unsigned int*>(IS_QUERY ? g_qlo4 : g_klo4);
    dhi[row * 32 + lane] = hi;
    dlo[row * 32 + lane] = lo;
    float d = fmaf(s1, s1, s2 * s2);
    #pragma unroll
    for (int o = 16; o; o >>= 1) d += __shfl_xor_sync(0xFFFFFFFFu, d, o);
    if (lane == 0) {
        if (IS_QUERY) g_diag_q[row] = 0.5f * d; else g_diag_k[row] = 0.5f * d;
    }
}

__global__ void __launch_bounds__(256) prep_p(const float* __restrict__ P)
{
    const int warp = threadIdx.x >> 5, lane = threadIdx.x & 31;
    const int row = blockIdx.x * 8 + warp;
    float s1 = 0.f, s2 = 0.f;
    if (row < MDIM) {
        float2 v = reinterpret_cast<const float2*>(P)[(size_t)row * 32 + lane];
        s1 = v.x; s2 = v.y;
    }
    uint32_t lo, hi = pack_split(s1, s2, lo);
    reinterpret_cast<unsigned int*>(g_phi4)[row * 32 + lane] = hi;
    reinterpret_cast<unsigned int*>(g_plo4)[row * 32 + lane] = lo;
}

// vT: [bh][e][i-pairs] split-bf16 from v[i][e]; smem 64x64 tile transpose
__global__ void __launch_bounds__(256) prep_vT(const float* __restrict__ V)
{
    const int bh = blockIdx.y, i0 = blockIdx.x * 64;
    const int tid = threadIdx.x;
    __shared__ float sm[64][65];
    const float4* Vb4 = reinterpret_cast<const float4*>(V + ((size_t)bh * SEQ + i0) * DDIM);
    #pragma unroll
    for (int t = 0; t < 4; t++) {
        int idx = tid + t * 256;               // float4 idx over 64x16
        int r = idx >> 4, e4 = (idx & 15) << 2;
        float4 v = Vb4[idx];
        sm[r][e4] = v.x; sm[r][e4+1] = v.y; sm[r][e4+2] = v.z; sm[r][e4+3] = v.w;
    }
    __syncthreads();
    #pragma unroll
    for (int t = 0; t < 8; t++) {
        int idx = tid + t * 256;               // word idx over 64 e x 32 ipairs
        int e = idx >> 5, ip = idx & 31;
        uint32_t lo, hi = pack_split(sm[2*ip][e], sm[2*ip+1][e], lo);
        size_t w = ((size_t)bh * VTR + e) * KPW + blockIdx.x * 32 + ip;
        g_vT_hi[w] = hi; g_vT_lo[w] = lo;
    }
}
// vT tail rows: e=64 -> ones (for kmean), e 65..71 -> zeros
__global__ void __launch_bounds__(256) prep_vT_tail()
{
    const size_t idx = (size_t)blockIdx.x * 256 + threadIdx.x;   // BHX*8*KPW
    if (idx >= (size_t)BHX * 8 * KPW) return;
    const size_t bh = idx / (8 * KPW);
    const int   r  = (int)((idx / KPW) % 8);
    const size_t w = ((size_t)bh * VTR + 64 + r) * KPW + (idx % KPW);
    g_vT_hi[w] = (r == 0) ? 0x3F803F80u : 0u;
    g_vT_lo[w] = 0u;
}

// ---------------------------------------------------------------------
// dash_mma: split-bf16 mma.sync, A = q/k hi/lo, B = P hi/lo (verified R16).
// KEY variant stores kd TRANSPOSED to g_dashT[j][i]; QUERY stores normal.
// ---------------------------------------------------------------------
template<bool IS_QUERY>
__global__ void __launch_bounds__(256) dash_mma()
{
    const int bh = blockIdx.y, r0 = blockIdx.x * 128;
    const int tid = threadIdx.x, warp = tid >> 5, lane = tid & 31;
    const int gid = lane >> 2, tig = lane & 3;

    const unsigned int* Ahi = reinterpret_cast<const unsigned int*>(IS_QUERY ? g_qhi4 : g_khi4)
                              + ((size_t)bh * SEQ + r0 + warp * 16) * 32;
    const unsigned int* Alo = reinterpret_cast<const unsigned int*>(IS_QUERY ? g_qlo4 : g_klo4)
                              + ((size_t)bh * SEQ + r0 + warp * 16) * 32;
    const unsigned int* Phi = reinterpret_cast<const unsigned int*>(g_phi4);
    const unsigned int* Plo = reinterpret_cast<const unsigned int*>(g_plo4);

    uint32_t ahi[16], alo[16];
    #pragma unroll
    for (int ks = 0; ks < 4; ks++) {
        int w = ks * 8 + tig;
        ahi[ks*4+0] = Ahi[gid * 32 + w];         alo[ks*4+0] = Alo[gid * 32 + w];
        ahi[ks*4+1] = Ahi[(gid+8) * 32 + w];     alo[ks*4+1] = Alo[(gid+8) * 32 + w];
        ahi[ks*4+2] = Ahi[gid * 32 + w + 4];     alo[ks*4+2] = Alo[gid * 32 + w + 4];
        ahi[ks*4+3] = Ahi[(gid+8) * 32 + w + 4]; alo[ks*4+3] = Alo[(gid+8) * 32 + w + 4];
    }

    const int i0 = r0 + warp * 16 + gid;         // this thread's first row
    const size_t row_g = (size_t)bh * SEQ + i0;
    float rm0 = -3.4e38f, rm1 = -3.4e38f;

    for (int nt = 0; nt < NTIL; nt++) {
        const int jb = nt * 8 + gid;
        float d[4] = {0.f, 0.f, 0.f, 0.f};
        #pragma unroll
        for (int ks = 0; ks < 4; ks++) {
            int w = jb * 32 + ks * 8 + tig;
            uint32_t bh2[2] = { Phi[w], Phi[w + 4] };
            uint32_t bl2[2] = { Plo[w], Plo[w + 4] };
            mma16816(d, &ahi[ks*4], bh2);
            mma16816(d, &ahi[ks*4], bl2);
            mma16816(d, &alo[ks*4], bh2);
        }
        const int c0 = nt * 8 + tig * 2;
        if (c0 < MDIM) {
            if (IS_QUERY) {
                float* dp0 = g_dash + row_g * MDIM;
                float* dp1 = g_dash + (row_g + 8) * MDIM;
                *reinterpret_cast<float2*>(dp0 + c0) = make_float2(d[0], d[1]);
                *reinterpret_cast<float2*>(dp1 + c0) = make_float2(d[2], d[3]);
            } else {
                float* tp = g_dashT + ((size_t)bh * JPAD + c0) * SEQ + i0;
                tp[0] = d[0];   tp[SEQ] = d[1];
                tp[8] = d[2];   tp[SEQ + 8] = d[3];
            }
            rm0 = fmaxf(rm0, fmaxf(d[0], d[1]));
            rm1 = fmaxf(rm1, fmaxf(d[2], d[3]));
        }
    }

    rm0 = fmaxf(rm0, __shfl_xor_sync(0xFFFFFFFFu, rm0, 1));
    rm0 = fmaxf(rm0, __shfl_xor_sync(0xFFFFFFFFu, rm0, 2));
    rm1 = fmaxf(rm1, __shfl_xor_sync(0xFFFFFFFFu, rm1, 1));
    rm1 = fmaxf(rm1, __shfl_xor_sync(0xFFFFFFFFu, rm1, 2));

    if (IS_QUERY) {
        if (tig == 0) {
            g_rowmax[row_g]     = rm0;
            g_rowmax[row_g + 8] = rm1;
        }
    } else {
        __shared__ float red[8];
        float wm = fmaxf(rm0, rm1);
        #pragma unroll
        for (int o = 16; o; o >>= 1) wm = fmaxf(wm, __shfl_xor_sync(0xFFFFFFFFu, wm, o));
        if (lane == 0) red[warp] = wm;
        __syncthreads();
        if (tid == 0) {
            float m = red[0];
            #pragma unroll
            for (int w = 1; w < 8; w++) m = fmaxf(m, red[w]);
            atomicMax(&g_kstab_bits, enc_f(m));
        }
    }
}

// ---------------------------------------------------------------------
// exp_prep_k: kpT[j][i] split-bf16 = RATIO*(exp(kdT - diag_k[i] - kstab)+EPS)
// grid (KPW/256, MDIM, BHX); coalesced both sides, no transpose needed.
// ---------------------------------------------------------------------
__global__ void __launch_bounds__(256) exp_prep_k()
{
    const int bh = blockIdx.z, j = blockIdx.y;
    const int ip = blockIdx.x * 256 + threadIdx.x;        // i-pair
    const float RATIO = 1.0f / sqrtf(266.0f);
    const float kstab = dec_f(g_kstab_bits);
    const size_t rb = ((size_t)bh * JPAD + j) * SEQ;
    float2 kd = *reinterpret_cast<const float2*>(g_dashT + rb + 2 * ip);
    float o0 = g_diag_k[bh * SEQ + 2 * ip]     + kstab;
    float o1 = g_diag_k[bh * SEQ + 2 * ip + 1] + kstab;
    float w0 = RATIO * (__expf(kd.x - o0) + EPSF);
    float w1 = RATIO * (__expf(kd.y - o1) + EPSF);
    uint32_t lo, hi = pack_split(w0, w1, lo);
    const size_t w = ((size_t)bh * JPAD + j) * KPW + ip;
    g_kpT_hi[w] = hi; g_kpT_lo[w] = lo;
}

// exp_prep_q: qp[i][j] split-bf16; zero for j >= MDIM (K-dim padding!)
__global__ void __launch_bounds__(256) exp_prep_q()
{
    const size_t idx = (size_t)blockIdx.x * 256 + threadIdx.x;  // BHX*SEQ*QPW
    if (idx >= (size_t)BHX * SEQ * QPW) return;
    const size_t row = idx / QPW;
    const int   w   = (int)(idx % QPW);
    const int   j0  = 2 * w;
    uint32_t hi = 0u, lo = 0u;
    if (j0 < MDIM) {                                     // MDIM even -> pair valid
        const float RATIO = 1.0f / sqrtf(266.0f);
        const float off = g_diag_q[row] + g_rowmax[row];
        const float* qd = g_dash + row * MDIM + j0;
        float w0 = RATIO * (__expf(qd[0] - off) + EPSF);
        float w1 = RATIO * (__expf(qd[1] - off) + EPSF);
        hi = pack_split(w0, w1, lo);
    }
    g_qp_hi[idx] = hi; g_qp_lo[idx] = lo;
}

// ---------------------------------------------------------------------
// ctx_mma: C[j][e(+kmean)] partials. A=kpT[j][i], B=vT[e][i]. split-K x8.
// ---------------------------------------------------------------------
__global__ void __launch_bounds__(256) ctx_mma()
{
    const int bh = blockIdx.z, kss = blockIdx.y;
    const int tid = threadIdx.x, warp = tid >> 5, lane = tid & 31;
    const int gid = lane >> 2, tig = lane & 3;
    const int j0 = (blockIdx.x * 8 + warp) * 16;
    if (j0 >= JPAD) return;                               // no syncthreads below
    const int rb2 = kss * (KROWS / 2);                    // i-pair base

    const unsigned int* Ahi = g_kpT_hi + ((size_t)bh * JPAD + j0) * KPW;
    const unsigned int* Alo = g_kpT_lo + ((size_t)bh * JPAD + j0) * KPW;
    const unsigned int* Bhi = g_vT_hi + (size_t)bh * VTR * KPW;
    const unsigned int* Blo = g_vT_lo + (size_t)bh * VTR * KPW;

    float d[9][4] = {};
    for (int ks = 0; ks < KROWS / 16; ks++) {
        const int w = rb2 + ks * 8 + tig;
        uint32_t ah[4], al[4];
        ah[0] = Ahi[gid * KPW + w];         al[0] = Alo[gid * KPW + w];
        ah[1] = Ahi[(gid+8) * KPW + w];     al[1] = Alo[(gid+8) * KPW + w];
        ah[2] = Ahi[gid * KPW + w + 4];     al[2] = Alo[gid * KPW + w + 4];
        ah[3] = Ahi[(gid+8) * KPW + w + 4]; al[3] = Alo[(gid+8) * KPW + w + 4];
        #pragma unroll
        for (int nt = 0; nt < 9; nt++) {
            const size_t bw = (size_t)(nt * 8 + gid) * KPW + w;
            uint32_t bh2[2] = { Bhi[bw], Bhi[bw + 4] };
            uint32_t bl2[2] = { Blo[bw], Blo[bw + 4] };
            mma16816(d[nt], ah, bh2);
            mma16816(d[nt], ah, bl2);
            mma16816(d[nt], al, bh2);
        }
    }

    float* base = g_ctx_part + (size_t)kss * CTXTOT;
    #pragma unroll
    for (int nt = 0; nt < 9; nt++) {
        const int c0 = nt * 8 + tig * 2;
        const int j = j0 + gid, j2 = j + 8;
        if (j < MDIM) {
            float* p = base + ((size_t)bh * MDIM + j) * CTXW;
            if (c0 < 64) { p[c0] = d[nt][0]; p[c0+1] = d[nt][1]; }
            else if (c0 == 64) p[64] = d[nt][0];
        }
        if (j2 < MDIM) {
            float* p = base + ((size_t)bh * MDIM + j2) * CTXW;
            if (c0 < 64) { p[c0] = d[nt][2]; p[c0+1] = d[nt][3]; }
            else if (c0 == 64) p[64] = d[nt][2];
        }
    }
}

__global__ void __launch_bounds__(256) ctx_reduce_kernel()
{
    const int idx4 = blockIdx.x * 256 + threadIdx.x;
    if (idx4 >= CTXTOT / 4) return;
    const float4* p0 = reinterpret_cast<const float4*>(g_ctx_part) + idx4;
    float4 s = *p0;
    #pragma unroll
    for (int ks = 1; ks < KSPL; ks++) {
        float4 t = *(p0 + (size_t)ks * (CTXTOT / 4));
        s.x += t.x; s.y += t.y; s.z += t.z; s.w += t.w;
    }
    const float invN = 1.0f / (float)SEQ;
    s.x *= invN; s.y *= invN; s.z *= invN; s.w *= invN;
    reinterpret_cast<float4*>(g_ctx)[idx4] = s;
}

// ctxT: [bh][e][j-pairs] split-bf16 from g_ctx[bh][j][e]; zeros for pads
__global__ void __launch_bounds__(256) prep_cT()
{
    const size_t idx = (size_t)blockIdx.x * 256 + threadIdx.x;  // BHX*VTR*CTW
    if (idx >= (size_t)BHX * VTR * CTW) return;
    const size_t bh = idx / (VTR * CTW);
    const int   e  = (int)((idx / CTW) % VTR);
    const int   w  = (int)(idx % CTW);
    const int   j0 = 2 * w;
    uint32_t hi = 0u, lo = 0u;
    if (e < 65 && j0 < MDIM) {
        const float* cb = g_ctx + (size_t)bh * MDIM * CTXW;
        float v0 = cb[(size_t)j0 * CTXW + e];
        float v1 = cb[(size_t)(j0 + 1) * CTXW + e];
        hi = pack_split(v0, v1, lo);
    }
    g_cT_hi[idx] = hi; g_cT_lo[idx] = lo;
}

// ---------------------------------------------------------------------
// out_mma: O[i][e] = Dinv * sum_j qp[i][j]*ctx[j][e]; den from e=64 col.
// A = qp[i][j], B = ctxT[e][j]. K=272 (17 steps).
// ---------------------------------------------------------------------
__global__ void __launch_bounds__(256) out_mma(float* __restrict__ Out)
{
    const int bh = blockIdx.y;
    const int tid = threadIdx.x, warp = tid >> 5, lane = tid & 31;
    const int gid = lane >> 2, tig = lane & 3;
    const int i0 = (blockIdx.x * 8 + warp) * 16;

    const unsigned int* Ahi = g_qp_hi + ((size_t)bh * SEQ + i0) * QPW;
    const unsigned int* Alo = g_qp_lo + ((size_t)bh * SEQ + i0) * QPW;
    const unsigned int* Bhi = g_cT_hi + (size_t)bh * VTR * CTW;
    const unsigned int* Blo = g_cT_lo + (size_t)bh * VTR * CTW;

    float d[9][4] = {};
    #pragma unroll
    for (int ks = 0; ks < JPAD / 16; ks++) {
        const int w = ks * 8 + tig;
        uint32_t ah[4], al[4];
        ah[0] = Ahi[gid * QPW + w];         al[0] = Alo[gid * QPW + w];
        ah[1] = Ahi[(gid+8) * QPW + w];     al[1] = Alo[(gid+8) * QPW + w];
        ah[2] = Ahi[gid * QPW + w + 4];     al[2] = Alo[gid * QPW + w + 4];
        ah[3] = Ahi[(gid+8) * QPW + w + 4]; al[3] = Alo[(gid+8) * QPW + w + 4];
        #pragma unroll
        for (int nt = 0; nt < 9; nt++) {
            const size_t bw = (size_t)(nt * 8 + gid) * CTW + w;
            uint32_t bh2[2] = { Bhi[bw], Bhi[bw + 4] };
            uint32_t bl2[2] = { Blo[bw], Blo[bw + 4] };
            mma16816(d[nt], ah, bh2);
            mma16816(d[nt], ah, bl2);
            mma16816(d[nt], al, bh2);
        }
    }

    // den at output col 64 = (nt 8, tig 0): broadcast from lane gid*4
    const float den0 = __shfl_sync(0xFFFFFFFFu, d[8][0], (lane & 28));
    const float den1 = __shfl_sync(0xFFFFFFFFu, d[8][2], (lane & 28));
    const float di0 = 1.0f / den0, di1 = 1.0f / den1;

    float* O0 = Out + ((size_t)bh * SEQ + i0 + gid) * DDIM;
    float* O1 = O0 + 8 * DDIM;
    #pragma unroll
    for (int nt = 0; nt < 8; nt++) {
        const int c0 = nt * 8 + tig * 2;
        *reinterpret_cast<float2*>(O0 + c0) = make_float2(di0 * d[nt][0], di0 * d[nt][1]);
        *reinterpret_cast<float2*>(O1 + c0) = make_float2(di1 * d[nt][2], di1 * d[nt][3]);
    }
}

// ---------------------------------------------------------------------
extern "C" void kernel_launch(void* const* d_in, const int* in_sizes, int n_in,
                              void* d_out, int out_size)
{
    const float* q = (const float*)d_in[0];
    const float* k = (const float*)d_in[1];
    const float* v = (const float*)d_in[2];
    const float* P = (const float*)d_in[3];
    float* out = (float*)d_out;

    reset_kernel<<<1, 1>>>();
    prep_p<<<PPAD / 8, 256>>>(P);
    prep_qk<false><<<BHX * SEQ / 8, 256>>>(k);
    prep_qk<true><<<BHX * SEQ / 8, 256>>>(q);
    prep_vT<<<dim3(SEQ / 64, BHX), 256>>>(v);
    prep_vT_tail<<<(BHX * 8 * KPW + 255) / 256, 256>>>();
    dash_mma<false><<<dim3(SEQ / 128, BHX), 256>>>();                 // kdT + kstab
    exp_prep_k<<<dim3(KPW / 256, MDIM, BHX), 256>>>();                // kpT hi/lo
    ctx_mma<<<dim3((JPAD + 127) / 128, KSPL, BHX), 256>>>();          // partials
    ctx_reduce_kernel<<<(CTXTOT / 4 + 255) / 256, 256>>>();           // g_ctx
    prep_cT<<<(int)(((size_t)BHX * VTR * CTW + 255) / 256), 256>>>(); // ctxT hi/lo
    dash_mma<true><<<dim3(SEQ / 128, BHX), 256>>>();                  // qd + rowmax
    exp_prep_q<<<(int)(((size_t)BHX * SEQ * QPW + 255) / 256), 256>>>();
    out_mma<<<dim3(SEQ / 128, BHX), 256>>>(out);                      // O + den
}